// round 9
// baseline (speedup 1.0000x reference)
#include <cuda_runtime.h>
#include <cstdint>

// state: [2, 4096, 512] float32. The 4 CNOTs compose into one bit-twiddle
// permutation of the 4096 row indices. GATHER: out[n,i,:] = in[n,src(i),:],
// rows = 512 floats = 2048 B contiguous.
//
// R8: v8.f32 (256-bit) accesses, 4 independent chunks per thread (MLP=4,
// all loads front-batched), 512 blocks x 256 threads (single wave).

static __device__ __forceinline__ unsigned src_index(unsigned j) {
    // PAIRS [(0,1),(2,3),(5,2),(11,7)] applied in reverse for the source map
    // (big-endian: qubit q -> bit 11-q)
    j ^= ((j >> 0) & 1u) << 4;    // (c=11, t=7)
    j ^= ((j >> 6) & 1u) << 9;    // (c=5,  t=2)
    j ^= ((j >> 9) & 1u) << 8;    // (c=2,  t=3)
    j ^= ((j >> 11) & 1u) << 10;  // (c=0,  t=1)
    return j;
}

// 2^19 v8 (32B) chunks total. 512 blocks x 256 threads x 4 chunks/thread.
// Chunk k at stride 2^17 -> all 4 loads independent; warp accesses stay
// fully contiguous (1 KB per warp per round).
__global__ __launch_bounds__(256) void cnot_perm_copy_v8x4(
    const float* __restrict__ in, float* __restrict__ out)
{
    unsigned base = blockIdx.x * blockDim.x + threadIdx.x;  // 0 .. 2^17-1

    const float* gsrc[4];
    float*       gdst[4];
    #pragma unroll
    for (int k = 0; k < 4; k++) {
        unsigned idx = base + (unsigned)k * (1u << 17);     // 0 .. 2^19-1
        unsigned c8  = idx & 63u;        // 32B chunk within row
        unsigned row = idx >> 6;         // 0 .. 8191
        unsigned i   = row & 4095u;
        unsigned n   = row >> 12;
        unsigned src = (n << 12) | src_index(i);
        gsrc[k] = in  + ((size_t)src * 512u + c8 * 8u);
        gdst[k] = out + ((size_t)row * 512u + c8 * 8u);
    }

    float v[4][8];
    #pragma unroll
    for (int k = 0; k < 4; k++) {
        asm volatile("ld.global.nc.v8.f32 {%0,%1,%2,%3,%4,%5,%6,%7}, [%8];"
            : "=f"(v[k][0]),"=f"(v[k][1]),"=f"(v[k][2]),"=f"(v[k][3]),
              "=f"(v[k][4]),"=f"(v[k][5]),"=f"(v[k][6]),"=f"(v[k][7])
            : "l"(gsrc[k]));
    }
    #pragma unroll
    for (int k = 0; k < 4; k++) {
        asm volatile("st.global.v8.f32 [%0], {%1,%2,%3,%4,%5,%6,%7,%8};"
            :: "l"(gdst[k]),
               "f"(v[k][0]),"f"(v[k][1]),"f"(v[k][2]),"f"(v[k][3]),
               "f"(v[k][4]),"f"(v[k][5]),"f"(v[k][6]),"f"(v[k][7])
            : "memory");
    }
}

extern "C" void kernel_launch(void* const* d_in, const int* in_sizes, int n_in,
                              void* d_out, int out_size) {
    const float* in  = (const float*)d_in[0];
    float*       out = (float*)d_out;
    // 2^19 chunks / (256 threads * 4) = 512 blocks (single wave)
    cnot_perm_copy_v8x4<<<512, 256>>>(in, out);
}